// round 6
// baseline (speedup 1.0000x reference)
#include <cuda_runtime.h>
#include <cuda_bf16.h>

#define NG 2048
#define HW 128
#define TILE_W 16
#define TILE_H 8
#define NCTA 128              // (128/16) x (128/8) tiles
#define NTHR 128
#define KCAP 512
#define TANFOV 0.5f
#define NEARP 0.2f
#define AMIN (1.0f/255.0f)
#define LOG2E 1.4426950408889634f
#define TEPS 1e-7f

// per-gaussian preprocessed data (unsorted, indexed by original id)
__device__ float4 g_cull[NG];  // px, py, cullR2, z
__device__ float4 g_a[NG];     // px, py, ca2, cb2
__device__ float4 g_b[NG];     // cc2, op, colR, colG
__device__ float  g_cb[NG];    // colB
// grid barrier (graph-replay safe: monotonic phase)
__device__ unsigned g_count;
__device__ unsigned g_phase;

__device__ __forceinline__ float fast_exp2(float x) {
    float r;
    asm("ex2.approx.f32 %0, %1;" : "=f"(r) : "f"(x));
    return r;
}

__global__ void __launch_bounds__(NTHR, 8) fused_kernel(
        const float* __restrict__ means3D,
        const float* __restrict__ colors,
        const float* __restrict__ opacities,
        const float* __restrict__ cov3Ds,
        const float* __restrict__ bg,
        float* __restrict__ out_img,
        float* __restrict__ out_radii) {
    __shared__ unsigned long long s_keys[KCAP];
    __shared__ float4 s_A[KCAP];
    __shared__ float4 s_B[KCAP];
    __shared__ float  s_Cb[KCAP];
    __shared__ int s_wcnt[4];
    __shared__ int s_n;
    __shared__ unsigned s_ph;

    int t = threadIdx.x;
    int bx = blockIdx.x;
    int w = t >> 5, lane = t & 31;

    if (t == 0) s_ph = *(volatile unsigned*)&g_phase;
    __syncthreads();
    unsigned myphase = s_ph;

    // ===== Phase 1: preprocess (CTAs 0..15, one gaussian per thread) =====
    if (bx < 16) {
        int i = bx * NTHR + t;
        const float fx = HW / (2.0f * TANFOV);
        const float fy = fx;

        float x = means3D[3*i + 0];
        float y = means3D[3*i + 1];
        float z = means3D[3*i + 2];
        float invz = 1.0f / z;

        float px = fx * x * invz + 0.5f * HW;
        float py = fy * y * invz + 0.5f * HW;

        const float lim = 1.3f * TANFOV;
        float txn = fminf(fmaxf(x * invz, -lim), lim) * z;
        float tyn = fminf(fmaxf(y * invz, -lim), lim) * z;

        float xx = cov3Ds[6*i+0], xy = cov3Ds[6*i+1], xz = cov3Ds[6*i+2];
        float yy = cov3Ds[6*i+3], yz = cov3Ds[6*i+4], zz = cov3Ds[6*i+5];

        float j00 = fx * invz;
        float j02 = -fx * txn * invz * invz;
        float j11 = fy * invz;
        float j12 = -fy * tyn * invz * invz;

        float M00 = j00*xx + j02*xz;
        float M01 = j00*xy + j02*yz;
        float M02 = j00*xz + j02*zz;
        float M11 = j11*yy + j12*yz;
        float M12 = j11*yz + j12*zz;

        float a = M00*j00 + M02*j02 + 0.3f;
        float b = M01*j11 + M02*j12;
        float c = M11*j11 + M12*j12 + 0.3f;

        float det = a*c - b*b;
        float invdet = 1.0f / det;
        float conA = c * invdet;
        float conB = -b * invdet;
        float conC = a * invdet;

        float mid = 0.5f * (a + c);
        float lam1 = mid + sqrtf(fmaxf(0.1f, mid*mid - det));

        bool valid = (z > NEARP) && (det > 0.0f);
        float radii = valid ? ceilf(3.0f * sqrtf(lam1)) : 0.0f;
        out_radii[i] = radii;

        float op = opacities[i];
        float cullR2;
        if (!valid) cullR2 = -1.0f;
        else {
            float tt = op * 255.0f;
            cullR2 = (tt <= 1.0f) ? -1.0f : 2.0f * lam1 * logf(tt);
        }

        g_cull[i] = make_float4(px, py, cullR2, z);
        g_a[i]    = make_float4(px, py, -0.5f*LOG2E*conA, -LOG2E*conB);
        g_b[i]    = make_float4(-0.5f*LOG2E*conC, op, colors[3*i+0], colors[3*i+1]);
        g_cb[i]   = colors[3*i+2];
    }

    // ===== grid barrier (128 CTAs, all resident) =====
    __syncthreads();
    if (t == 0) {
        __threadfence();
        unsigned old = atomicAdd(&g_count, 1u);
        if (old == NCTA - 1) {
            g_count = 0;
            __threadfence();
            atomicAdd(&g_phase, 1u);
        } else {
            while (*(volatile unsigned*)&g_phase == myphase) __nanosleep(20);
        }
        __threadfence();
    }
    __syncthreads();

    // ===== Phase 2: per-tile cull -> compact -> sort -> blend =====
    int tx0 = (bx & 7) * TILE_W;
    int ty0 = (bx >> 3) * TILE_H;
    float rx0 = (float)tx0, rx1 = (float)(tx0 + TILE_W - 1);
    float ry0 = (float)ty0, ry1 = (float)(ty0 + TILE_H - 1);

    // pass A: count survivors (16 gaussians per thread)
    unsigned keepmask = 0u;
    int cnt = 0;
    #pragma unroll 4
    for (int k = 0; k < 16; k++) {
        int g = (k << 7) | t;
        float4 cu = g_cull[g];
        float ddx = fmaxf(0.0f, fmaxf(rx0 - cu.x, cu.x - rx1));
        float ddy = fmaxf(0.0f, fmaxf(ry0 - cu.y, cu.y - ry1));
        bool keep = (ddx*ddx + ddy*ddy) <= cu.z;
        keepmask |= (unsigned)keep << k;
        cnt += keep;
    }

    // CTA exclusive scan of cnt
    int inc = cnt;
    #pragma unroll
    for (int d = 1; d < 32; d <<= 1) {
        int v = __shfl_up_sync(0xffffffffu, inc, d);
        if (lane >= d) inc += v;
    }
    if (lane == 31) s_wcnt[w] = inc;
    __syncthreads();
    int base = inc - cnt;
    #pragma unroll
    for (int ww = 0; ww < 4; ww++) base += (ww < w) ? s_wcnt[ww] : 0;
    if (t == 0) {
        int tot = s_wcnt[0] + s_wcnt[1] + s_wcnt[2] + s_wcnt[3];
        s_n = (tot < KCAP) ? tot : KCAP;
    }

    // pass B: store keys (zbits<<32 | idx) at scanned positions
    int pos = base;
    #pragma unroll 4
    for (int k = 0; k < 16; k++) {
        if ((keepmask >> k) & 1u) {
            int g = (k << 7) | t;
            float zv = g_cull[g].w;          // L1 hit
            if (pos < KCAP)
                s_keys[pos] = ((unsigned long long)__float_as_uint(zv) << 32)
                              | (unsigned)g;
            pos++;
        }
    }
    __syncthreads();

    int n = s_n;
    int npad = 1;
    while (npad < n) npad <<= 1;

    // pad
    for (int i = n + t; i < npad; i += NTHR)
        s_keys[i] = 0xFFFFFFFFFFFFFFFFull;
    __syncthreads();

    // bitonic sort ascending (z, then idx) — matches stable argsort
    for (int k = 2; k <= npad; k <<= 1) {
        for (int j = k >> 1; j > 0; j >>= 1) {
            for (int i = t; i < npad; i += NTHR) {
                int l = i ^ j;
                if (l > i) {
                    unsigned long long va = s_keys[i];
                    unsigned long long vb = s_keys[l];
                    bool up = ((i & k) == 0);
                    if (up ? (va > vb) : (va < vb)) {
                        s_keys[i] = vb;
                        s_keys[l] = va;
                    }
                }
            }
            __syncthreads();
        }
    }

    // gather survivor data in sorted order
    for (int i = t; i < n; i += NTHR) {
        int gi = (int)(s_keys[i] & 0xFFFFFFFFu);
        s_A[i]  = g_a[gi];
        s_B[i]  = g_b[gi];
        s_Cb[i] = g_cb[gi];
    }
    __syncthreads();

    // blend front-to-back, one pixel per thread
    float X = (float)(tx0 + (t & 15));
    float Y = (float)(ty0 + (t >> 4));
    float T = 1.0f, accr = 0.0f, accg = 0.0f, accb = 0.0f;

    for (int j = 0; j < n; j++) {
        if ((j & 3) == 0 &&
            __ballot_sync(0xffffffffu, T >= TEPS) == 0u) break;
        float4 a  = s_A[j];
        float4 bb = s_B[j];
        float cb  = s_Cb[j];
        float dx = a.x - X;
        float dy = a.y - Y;
        float p2 = a.z*dx*dx + a.w*dx*dy + bb.x*dy*dy;  // power * log2(e)
        float e = fast_exp2(p2);
        float alpha = fminf(bb.y * e, 0.99f);
        if (p2 > 0.0f || alpha < AMIN) alpha = 0.0f;
        float wgt = alpha * T;
        accr = fmaf(wgt, bb.z, accr);
        accg = fmaf(wgt, bb.w, accg);
        accb = fmaf(wgt, cb,   accb);
        T = fmaf(-alpha, T, T);
    }

    int p = (ty0 + (t >> 4)) * HW + tx0 + (t & 15);
    out_img[p]           = fmaf(T, bg[0], accr);
    out_img[HW*HW + p]   = fmaf(T, bg[1], accg);
    out_img[2*HW*HW + p] = fmaf(T, bg[2], accb);
}

extern "C" void kernel_launch(void* const* d_in, const int* in_sizes, int n_in,
                              void* d_out, int out_size) {
    const float* means3D   = (const float*)d_in[0];
    const float* colors    = (const float*)d_in[1];
    const float* opacities = (const float*)d_in[2];
    const float* cov3Ds    = (const float*)d_in[3];
    const float* bg        = (const float*)d_in[4];
    float* out = (float*)d_out;
    float* out_img   = out;              // 3*128*128
    float* out_radii = out + 3*HW*HW;    // 2048

    fused_kernel<<<NCTA, NTHR>>>(means3D, colors, opacities, cov3Ds, bg,
                                 out_img, out_radii);
}

// round 8
// speedup vs baseline: 2.5462x; 2.5462x over previous
#include <cuda_runtime.h>
#include <cuda_bf16.h>

#define NG 2048
#define HW 128
#define TANFOV 0.5f
#define NEARP 0.2f
#define AMIN (1.0f/255.0f)
#define LOG2E 1.4426950408889634f
#define TEPS 1e-7f
#define CHUNKS 8
#define CHSZ (NG/CHUNKS)      // 256
#define NCTA 512              // 64 tiles x 8 chunks; also 512*4 = 2048 rank warps

// preprocessed, depth-sorted (indexed by rank)
__device__ float4 g_cull[NG];  // px, py, cullR2, pad   (cull-only read)
__device__ float4 g_a[NG];     // px, py, ca2, cb2
__device__ float4 g_bb[NG];    // cc2, op, colR, colG
__device__ float  g_cbl[NG];   // colB
// per-chunk partial (r,g,b,T) per pixel
__device__ float4 g_part[CHUNKS][HW*HW];
// grid barrier (graph-replay safe: monotonic phase)
__device__ unsigned g_count;
__device__ unsigned g_phase;
// per-tile arrival counters (monotonic; last of each run sees old%CHUNKS==CHUNKS-1)
__device__ unsigned g_tile_cnt[64];

__device__ __forceinline__ float fast_exp2(float x) {
    float r;
    asm("ex2.approx.f32 %0, %1;" : "=f"(r) : "f"(x));
    return r;
}

__global__ void __launch_bounds__(256, 4) fused_kernel(
        const float* __restrict__ means3D,
        const float* __restrict__ colors,
        const float* __restrict__ opacities,
        const float* __restrict__ cov3Ds,
        const float* __restrict__ bg,
        float* __restrict__ out_img,
        float* __restrict__ out_radii) {
    // smem union: phase1 z-stage (8KB) | phase2 survivor arrays (~9.2KB)
    __shared__ __align__(16) char sraw[9472];
    float*  s_z  = (float*)sraw;                    // 2048 floats = 8KB
    float4* s_A  = (float4*)sraw;                   // 256*16 = 4096
    float4* s_B  = (float4*)(sraw + 4096);          // 256*16 = 4096
    float*  s_Cb = (float*)(sraw + 8192);           // 256*4  = 1024
    int*    s_cnt = (int*)(sraw + 9216);            // 8 ints
    __shared__ unsigned s_ph;
    __shared__ unsigned s_last;

    int t = threadIdx.x;
    int bx = blockIdx.x;
    int w = t >> 5, lane = t & 31;

    if (t == 0) s_ph = *(volatile unsigned*)&g_phase;
    __syncthreads();
    unsigned myphase = s_ph;

    // ===== Phase 1: stage z -> rank (4 warps, 1 gaussian each) -> preprocess =====
    {
        #pragma unroll
        for (int k = 0; k < 8; k++) {
            int j = t + (k << 8);
            s_z[j] = __ldg(&means3D[3*j + 2]);
        }
        __syncthreads();

        if (w < 4) {
            int i = bx * 4 + w;                  // gaussian for this warp
            float zi = s_z[i];

            // stable rank from smem (conflict-free lane-consecutive access)
            int cnt = 0;
            #pragma unroll 8
            for (int j = lane; j < NG; j += 32) {
                float zj = s_z[j];
                cnt += (zj < zi) || (zj == zi && j < i);
            }
            int rank = __reduce_add_sync(0xffffffffu, cnt);

            const float fx = HW / (2.0f * TANFOV);
            const float fy = fx;

            float x = __ldg(&means3D[3*i + 0]);
            float y = __ldg(&means3D[3*i + 1]);
            float z = zi;
            float invz = 1.0f / z;

            float px = fx * x * invz + 0.5f * HW;
            float py = fy * y * invz + 0.5f * HW;

            const float lim = 1.3f * TANFOV;
            float txn = fminf(fmaxf(x * invz, -lim), lim) * z;
            float tyn = fminf(fmaxf(y * invz, -lim), lim) * z;

            float xx = __ldg(&cov3Ds[6*i+0]), xy = __ldg(&cov3Ds[6*i+1]);
            float xz = __ldg(&cov3Ds[6*i+2]), yy = __ldg(&cov3Ds[6*i+3]);
            float yz = __ldg(&cov3Ds[6*i+4]), zz = __ldg(&cov3Ds[6*i+5]);

            float j00 = fx * invz;
            float j02 = -fx * txn * invz * invz;
            float j11 = fy * invz;
            float j12 = -fy * tyn * invz * invz;

            float M00 = j00*xx + j02*xz;
            float M01 = j00*xy + j02*yz;
            float M02 = j00*xz + j02*zz;
            float M11 = j11*yy + j12*yz;
            float M12 = j11*yz + j12*zz;

            float a = M00*j00 + M02*j02 + 0.3f;
            float b = M01*j11 + M02*j12;
            float c = M11*j11 + M12*j12 + 0.3f;

            float det = a*c - b*b;
            float invdet = 1.0f / det;
            float conA = c * invdet;
            float conB = -b * invdet;
            float conC = a * invdet;

            float mid = 0.5f * (a + c);
            float lam1 = mid + sqrtf(fmaxf(0.1f, mid*mid - det));

            bool valid = (z > NEARP) && (det > 0.0f);
            float radii = valid ? ceilf(3.0f * sqrtf(lam1)) : 0.0f;

            float op = __ldg(&opacities[i]);
            float cullR2;
            if (!valid) cullR2 = -1.0f;
            else {
                float tt = op * 255.0f;
                cullR2 = (tt <= 1.0f) ? -1.0f : 2.0f * lam1 * logf(tt);
            }

            if (lane == 0) {
                out_radii[i] = radii;
                g_cull[rank] = make_float4(px, py, cullR2, 0.0f);
                g_a[rank]    = make_float4(px, py, -0.5f*LOG2E*conA, -LOG2E*conB);
                g_bb[rank]   = make_float4(-0.5f*LOG2E*conC, op,
                                           __ldg(&colors[3*i+0]), __ldg(&colors[3*i+1]));
                g_cbl[rank]  = __ldg(&colors[3*i+2]);
            }
        }
    }

    // ===== grid barrier (512 CTAs, residency guaranteed by launch_bounds) =====
    __syncthreads();
    if (t == 0) {
        __threadfence();
        unsigned old = atomicAdd(&g_count, 1u);
        if (old == NCTA - 1) {
            g_count = 0;
            __threadfence();
            atomicAdd(&g_phase, 1u);
        } else {
            while (*(volatile unsigned*)&g_phase == myphase) __nanosleep(20);
        }
        __threadfence();
    }
    __syncthreads();

    // ===== Phase 2: tiled blend (tile, depth-chunk) + per-tile combine =====
    int tile  = bx & 63;
    int chunk = bx >> 6;
    int tx0 = (tile & 7) * 16;
    int ty0 = (tile >> 3) * 16;
    float X = (float)(tx0 + (t & 15));
    float Y = (float)(ty0 + (t >> 4));
    float rx0 = (float)tx0, rx1 = (float)(tx0 + 15);
    float ry0 = (float)ty0, ry1 = (float)(ty0 + 15);

    int gi = chunk * CHSZ + t;
    float4 cu = g_cull[gi];
    float ddx = fmaxf(0.0f, fmaxf(rx0 - cu.x, cu.x - rx1));
    float ddy = fmaxf(0.0f, fmaxf(ry0 - cu.y, cu.y - ry1));
    bool keep = (ddx*ddx + ddy*ddy) <= cu.z;   // cullR2 < 0 => skip

    unsigned bal = __ballot_sync(0xffffffffu, keep);
    if (lane == 0) s_cnt[w] = __popc(bal);
    __syncthreads();

    int off = 0, total = 0;
    #pragma unroll
    for (int k = 0; k < 8; k++) {
        int cn = s_cnt[k];
        off += (k < w) ? cn : 0;
        total += cn;
    }
    int pos = off + __popc(bal & ((1u << lane) - 1u));
    if (keep) {
        s_A[pos]  = g_a[gi];
        s_B[pos]  = g_bb[gi];
        s_Cb[pos] = g_cbl[gi];
    }
    __syncthreads();

    float T = 1.0f, accr = 0.0f, accg = 0.0f, accb = 0.0f;
    for (int j = 0; j < total; j++) {
        if ((j & 7) == 0 &&
            __ballot_sync(0xffffffffu, T >= TEPS) == 0u) break;
        float4 a  = s_A[j];
        float4 b4 = s_B[j];
        float cb  = s_Cb[j];
        float dx = a.x - X;
        float dy = a.y - Y;
        float p2 = a.z*dx*dx + a.w*dx*dy + b4.x*dy*dy;  // power * log2(e)
        float e = fast_exp2(p2);
        float alpha = fminf(b4.y * e, 0.99f);
        if (p2 > 0.0f || alpha < AMIN) alpha = 0.0f;
        float wgt = alpha * T;
        accr = fmaf(wgt, b4.z, accr);
        accg = fmaf(wgt, b4.w, accg);
        accb = fmaf(wgt, cb,   accb);
        T = fmaf(-alpha, T, T);
    }

    int p = (ty0 + (t >> 4)) * HW + tx0 + (t & 15);
    g_part[chunk][p] = make_float4(accr, accg, accb, T);

    // last arriving chunk-CTA of this tile folds the 8 partials
    __syncthreads();
    if (t == 0) {
        __threadfence();
        unsigned old = atomicAdd(&g_tile_cnt[tile], 1u);
        s_last = ((old & (CHUNKS-1u)) == CHUNKS-1u) ? 1u : 0u;
    }
    __syncthreads();

    if (s_last) {
        __threadfence();   // acquire: all 8 partials visible
        float Tc = 1.0f, r = 0.0f, g = 0.0f, b = 0.0f;
        #pragma unroll
        for (int k = 0; k < CHUNKS; k++) {
            float4 c = __ldcg(&g_part[k][p]);
            r = fmaf(Tc, c.x, r);
            g = fmaf(Tc, c.y, g);
            b = fmaf(Tc, c.z, b);
            Tc *= c.w;
        }
        out_img[p]           = fmaf(Tc, bg[0], r);
        out_img[HW*HW + p]   = fmaf(Tc, bg[1], g);
        out_img[2*HW*HW + p] = fmaf(Tc, bg[2], b);
    }
}

extern "C" void kernel_launch(void* const* d_in, const int* in_sizes, int n_in,
                              void* d_out, int out_size) {
    const float* means3D   = (const float*)d_in[0];
    const float* colors    = (const float*)d_in[1];
    const float* opacities = (const float*)d_in[2];
    const float* cov3Ds    = (const float*)d_in[3];
    const float* bg        = (const float*)d_in[4];
    float* out = (float*)d_out;
    float* out_img   = out;              // 3*128*128
    float* out_radii = out + 3*HW*HW;    // 2048

    fused_kernel<<<NCTA, 256>>>(means3D, colors, opacities, cov3Ds, bg,
                                out_img, out_radii);
}